// round 12
// baseline (speedup 1.0000x reference)
#include <cuda_runtime.h>

#define Bz 256
#define Nz 4096
#define Mz 64
#define Cz 512
#define G4 2048
#define Kcat 832     // IN(64) + H*M(256) + C(512)
#define PN 560       // 8 * 70
#define EAN 512      // 4 * 128
#define NTILES 16    // Nz / 256

// ---------------- scratch (static device globals; no allocation) -------------
__device__ float d_gatesP[2 * (size_t)Bz * G4];   // 2 K-splits
__device__ float d_PpP[4 * (size_t)Bz * PN];      // 4 K-splits
__device__ float d_EApP[4 * (size_t)Bz * EAN];
__device__ float d_cst[Bz * Cz];
__device__ float d_hst[Bz * Cz];
__device__ float d_key[8 * Bz * Mz];
__device__ float d_knorm[8 * Bz];
__device__ float d_betaA[8 * Bz];
__device__ float d_gateA[8 * Bz];
__device__ float d_gammaA[8 * Bz];
__device__ float d_shiftA[8 * Bz * 3];
__device__ float d_eA[4 * Bz * Mz];
__device__ float d_aA[4 * Bz * Mz];
__device__ float d_dotr[(size_t)Bz * Nz];
__device__ float d_dotw[(size_t)Bz * Nz];
__device__ float d_rn[(size_t)Bz * Nz];
__device__ float d_ww[3 * (size_t)Bz * Nz];   // write weights, pairs 0..2 (pair3 write is dead)
__device__ float d_wr[4 * (size_t)Bz * Nz];   // read weights, pairs 0..3
__device__ float d_readpart[4 * NTILES * Bz * Mz];
__device__ float d_reads[4 * Bz * Mz];

// ---------------- helpers ----------------------------------------------------
__device__ __forceinline__ float sigm(float x) { return 1.f / (1.f + __expf(-x)); }
__device__ __forceinline__ float softplusf(float x) {
    return (x > 20.f) ? x : log1pf(__expf(x));
}

// ---------------- gates GEMM (xcat assembled on the fly, K-split 2) ----------
__global__ void gemm_gates(const float* __restrict__ W_ih,
                           const float* __restrict__ W_hh,
                           const float* __restrict__ in_data,
                           const float* __restrict__ prev_reads,
                           const float* __restrict__ h0) {
    __shared__ float As[16][64];
    __shared__ float Ws[16][64];
    int tid = threadIdx.x;
    int tx = tid & 15, ty = tid >> 4;
    int m0 = blockIdx.y * 64;
    int j0 = blockIdx.x * 64;
    int z = blockIdx.z;                 // K-split 0/1
    int kbeg = z * 416, kend = kbeg + 416;
    int lrow = tid >> 2;
    int lk4 = (tid & 3) * 4;

    float acc[4][4] = {};
    for (int k0 = kbeg; k0 < kend; k0 += 16) {
        int m = m0 + lrow;
        int k = k0 + lk4;
        float4 av;
        if (k < 64) {
            av = *(const float4*)&in_data[m * 64 + k];
        } else if (k < 320) {
            int i = (k - 64) >> 6, mm = (k - 64) & 63;
            av = *(const float4*)&prev_reads[(i * Bz + m) * 64 + mm];
        } else {
            av = *(const float4*)&h0[m * Cz + (k - 320)];
        }
        As[lk4 + 0][lrow] = av.x; As[lk4 + 1][lrow] = av.y;
        As[lk4 + 2][lrow] = av.z; As[lk4 + 3][lrow] = av.w;
        int j = j0 + lrow;
        const float* src; int kl;
        if (k0 < 320) { src = W_ih + (size_t)j * 320; kl = k0; }
        else          { src = W_hh + (size_t)j * 512; kl = k0 - 320; }
        float4 wv = *(const float4*)&src[kl + lk4];
        Ws[lk4 + 0][lrow] = wv.x; Ws[lk4 + 1][lrow] = wv.y;
        Ws[lk4 + 2][lrow] = wv.z; Ws[lk4 + 3][lrow] = wv.w;
        __syncthreads();
#pragma unroll
        for (int kk = 0; kk < 16; ++kk) {
            float4 a4 = *(const float4*)&As[kk][ty * 4];
            float4 w4 = *(const float4*)&Ws[kk][tx * 4];
            acc[0][0] += a4.x * w4.x; acc[0][1] += a4.x * w4.y;
            acc[0][2] += a4.x * w4.z; acc[0][3] += a4.x * w4.w;
            acc[1][0] += a4.y * w4.x; acc[1][1] += a4.y * w4.y;
            acc[1][2] += a4.y * w4.z; acc[1][3] += a4.y * w4.w;
            acc[2][0] += a4.z * w4.x; acc[2][1] += a4.z * w4.y;
            acc[2][2] += a4.z * w4.z; acc[2][3] += a4.z * w4.w;
            acc[3][0] += a4.w * w4.x; acc[3][1] += a4.w * w4.y;
            acc[3][2] += a4.w * w4.z; acc[3][3] += a4.w * w4.w;
        }
        __syncthreads();
    }
    float* out = d_gatesP + (size_t)z * Bz * G4;
#pragma unroll
    for (int i = 0; i < 4; ++i) {
        int m = m0 + ty * 4 + i;
#pragma unroll
        for (int jj = 0; jj < 4; ++jj)
            out[(size_t)m * G4 + j0 + tx * 4 + jj] = acc[i][jj];
    }
}

// ---------------- addressing GEMMs (P + EA, K-split 4) ------------------------
__global__ void gemm_addr(const float* __restrict__ W_addr,
                          const float* __restrict__ W_ea) {
    int z = blockIdx.z;
    int tgt = z >> 2, ks = z & 3;
    if (tgt == 1 && blockIdx.x >= EAN / 64) return;
    const float* W = tgt ? W_ea : W_addr;
    int Nc = tgt ? EAN : PN;
    float* out = tgt ? (d_EApP + (size_t)ks * Bz * EAN)
                     : (d_PpP + (size_t)ks * Bz * PN);
    int kbeg = ks * 128, kend = kbeg + 128;

    __shared__ float As[16][64];
    __shared__ float Ws[16][64];
    int tid = threadIdx.x;
    int tx = tid & 15, ty = tid >> 4;
    int m0 = blockIdx.y * 64;
    int j0 = blockIdx.x * 64;
    int lrow = tid >> 2;
    int lk4 = (tid & 3) * 4;

    float acc[4][4] = {};
    for (int k0 = kbeg; k0 < kend; k0 += 16) {
        float4 av = *(const float4*)&d_cst[(size_t)(m0 + lrow) * Cz + k0 + lk4];
        As[lk4 + 0][lrow] = av.x; As[lk4 + 1][lrow] = av.y;
        As[lk4 + 2][lrow] = av.z; As[lk4 + 3][lrow] = av.w;
        int j = j0 + lrow;
        float4 wv = make_float4(0.f, 0.f, 0.f, 0.f);
        if (j < Nc) wv = *(const float4*)&W[(size_t)j * Cz + k0 + lk4];
        Ws[lk4 + 0][lrow] = wv.x; Ws[lk4 + 1][lrow] = wv.y;
        Ws[lk4 + 2][lrow] = wv.z; Ws[lk4 + 3][lrow] = wv.w;
        __syncthreads();
#pragma unroll
        for (int kk = 0; kk < 16; ++kk) {
            float4 a4 = *(const float4*)&As[kk][ty * 4];
            float4 w4 = *(const float4*)&Ws[kk][tx * 4];
            acc[0][0] += a4.x * w4.x; acc[0][1] += a4.x * w4.y;
            acc[0][2] += a4.x * w4.z; acc[0][3] += a4.x * w4.w;
            acc[1][0] += a4.y * w4.x; acc[1][1] += a4.y * w4.y;
            acc[1][2] += a4.y * w4.z; acc[1][3] += a4.y * w4.w;
            acc[2][0] += a4.z * w4.x; acc[2][1] += a4.z * w4.y;
            acc[2][2] += a4.z * w4.z; acc[2][3] += a4.z * w4.w;
            acc[3][0] += a4.w * w4.x; acc[3][1] += a4.w * w4.y;
            acc[3][2] += a4.w * w4.z; acc[3][3] += a4.w * w4.w;
        }
        __syncthreads();
    }
#pragma unroll
    for (int i = 0; i < 4; ++i) {
        int m = m0 + ty * 4 + i;
#pragma unroll
        for (int jj = 0; jj < 4; ++jj) {
            int j = j0 + tx * 4 + jj;
            if (j < Nc) out[(size_t)m * Nc + j] = acc[i][jj];
        }
    }
}

// ---------------- LSTM activations (sums K-split partials + bias) -------------
__global__ void lstm_act(const float* __restrict__ c0,
                         const float* __restrict__ b_ih,
                         const float* __restrict__ b_hh) {
    int idx = blockIdx.x * 256 + threadIdx.x;   // Bz*Cz
    int b = idx >> 9, j = idx & 511;
    const size_t off2 = (size_t)Bz * G4;
    const float* g0 = d_gatesP + (size_t)b * G4;
    const float* g1 = d_gatesP + off2 + (size_t)b * G4;
    float ig = g0[j]        + g1[j]        + b_ih[j]        + b_hh[j];
    float fg = g0[512 + j]  + g1[512 + j]  + b_ih[512 + j]  + b_hh[512 + j];
    float gg = g0[1024 + j] + g1[1024 + j] + b_ih[1024 + j] + b_hh[1024 + j];
    float og = g0[1536 + j] + g1[1536 + j] + b_ih[1536 + j] + b_hh[1536 + j];
    float c = sigm(fg) * c0[idx] + sigm(ig) * tanhf(gg);
    d_cst[idx] = c;
    d_hst[idx] = sigm(og) * tanhf(c);
}

// ---------------- per-head derived parameters (sums K-split partials) ---------
// Runs AFTER pass0 (which computes its own pair-0 keys from d_PpP directly).
__global__ void head_params(const float* __restrict__ b_addr,
                            const float* __restrict__ b_ea) {
    int hi = blockIdx.x, b = blockIdx.y, m = threadIdx.x;   // 64 threads
    __shared__ float sm[64];

    float pv = b_addr[hi * 70 + m];
#pragma unroll
    for (int s = 0; s < 4; ++s)
        pv += d_PpP[(size_t)s * Bz * PN + (size_t)b * PN + hi * 70 + m];
    float k = tanhf(pv);
    d_key[(hi * Bz + b) * 64 + m] = k;
    sm[m] = k * k;
    __syncthreads();
    for (int s = 32; s; s >>= 1) { if (m < s) sm[m] += sm[m + s]; __syncthreads(); }
    if (m == 0) {
        float tail[6];
#pragma unroll
        for (int t = 0; t < 6; ++t) {
            float v = b_addr[hi * 70 + 64 + t];
#pragma unroll
            for (int s = 0; s < 4; ++s)
                v += d_PpP[(size_t)s * Bz * PN + (size_t)b * PN + hi * 70 + 64 + t];
            tail[t] = v;
        }
        d_knorm[hi * Bz + b] = sqrtf(sm[0]);
        d_betaA[hi * Bz + b] = softplusf(tail[0]);
        d_gateA[hi * Bz + b] = sigm(tail[1]);
        float a0 = tail[2], a1 = tail[3], a2 = tail[4];
        float mx = fmaxf(a0, fmaxf(a1, a2));
        float e0 = __expf(a0 - mx), e1 = __expf(a1 - mx), e2 = __expf(a2 - mx);
        float is = 1.f / (e0 + e1 + e2);
        d_shiftA[(hi * Bz + b) * 3 + 0] = e0 * is;
        d_shiftA[(hi * Bz + b) * 3 + 1] = e1 * is;
        d_shiftA[(hi * Bz + b) * 3 + 2] = e2 * is;
        d_gammaA[hi * Bz + b] = 1.f + softplusf(tail[5]);
    }
    if (hi < 4) {
        float e = b_ea[hi * 128 + m];
        float a = b_ea[hi * 128 + 64 + m];
#pragma unroll
        for (int s = 0; s < 4; ++s) {
            e += d_EApP[(size_t)s * Bz * EAN + (size_t)b * EAN + hi * 128 + m];
            a += d_EApP[(size_t)s * Bz * EAN + (size_t)b * EAN + hi * 128 + 64 + m];
        }
        d_eA[(hi * Bz + b) * 64 + m] = sigm(e);
        d_aA[(hi * Bz + b) * 64 + m] = tanhf(a);
    }
}

// ---------------- big memory passes (scalar FMA, per-pass occupancy) ----------
// Pass L: recompute chain of writes 0..L-2 from mem0; read with wr[L-1];
// apply write L-1; dots for pair L (skip write-head dot at L==3; none at L==4).
// Pass 0 computes its own keys from d_PpP (head_params runs after it).
template <int L>
__global__ void __launch_bounds__(256, (L == 0) ? 4 : ((L == 3) ? 2 : 3))
pass_kernel(const float* __restrict__ mem0, const float* __restrict__ b_addr) {
    const int b = blockIdx.y;
    const int n0 = blockIdx.x * 256;
    const int tid = threadIdx.x;
    const int g = tid >> 4, t = tid & 15;
    const int tm = t * 4;
    const size_t bN = (size_t)b * Nz;

    __shared__ float e_s[3][64], a_s[3][64];
    __shared__ float kr_s[64], kw_s[64];
    __shared__ float red[16][64];

    constexpr int NH  = (L < 3) ? L : 3;         // e/a vectors 0..NH-1
    constexpr int NWS = (L < 3) ? L : 3;         // ww streams read
    constexpr bool DOTS = (L <= 3);
    constexpr bool DOTW = (L < 3);
    constexpr int JA = (L >= 1) ? (L - 1) : 0;   // applied write index

    for (int idx = tid; idx < NH * 64; idx += 256) {
        int j = idx >> 6, m = idx & 63;
        e_s[j][m] = d_eA[(j * Bz + b) * 64 + m];
        a_s[j][m] = d_aA[(j * Bz + b) * 64 + m];
    }
    if (L == 0) {
        // self-compute pair-0 keys from GEMM partials (head_params not yet run)
        if (tid < 128) {
            int hi = tid >> 6, m = tid & 63;
            float pv = b_addr[hi * 70 + m];
#pragma unroll
            for (int s = 0; s < 4; ++s)
                pv += d_PpP[(size_t)s * Bz * PN + (size_t)b * PN + hi * 70 + m];
            float k = tanhf(pv);
            if (hi == 0) kr_s[m] = k; else kw_s[m] = k;
        }
    } else if (DOTS) {
        if (tid < 64) kr_s[tid] = d_key[((2 * L) * Bz + b) * 64 + tid];
        else if (DOTW && tid < 128)
            kw_s[tid - 64] = d_key[((2 * L + 1) * Bz + b) * 64 + (tid - 64)];
    }
    __syncthreads();

    // hoist per-column params to registers (scalar)
    float ne[NH > 0 ? NH : 1][4], aa[NH > 0 ? NH : 1][4];
#pragma unroll
    for (int j = 0; j < NH; ++j)
#pragma unroll
        for (int x = 0; x < 4; ++x) {
            ne[j][x] = -e_s[j][tm + x];
            aa[j][x] =  a_s[j][tm + x];
        }
    float kr[4] = {}, kw[4] = {};
    if (DOTS) {
#pragma unroll
        for (int x = 0; x < 4; ++x) kr[x] = kr_s[tm + x];
        if (DOTW)
#pragma unroll
            for (int x = 0; x < 4; ++x) kw[x] = kw_s[tm + x];
    }

    float r0 = 0.f, r1 = 0.f, r2 = 0.f, r3 = 0.f;
    const float* base = mem0 + (((size_t)(bN + n0)) << 6);

#pragma unroll
    for (int rr = 0; rr < 4; ++rr) {
        const int nb = rr * 64;
        float4 v[4];
        float wj[NWS > 0 ? NWS : 1][4];
        float wrv[4];
        // ---- batch ALL global loads first (MLP >= 4) ----
#pragma unroll
        for (int u = 0; u < 4; ++u) {
            int row = nb + u * 16 + g;
            v[u] = *(const float4*)(base + (((size_t)row) << 6) + tm);
        }
#pragma unroll
        for (int u = 0; u < 4; ++u) {
            int n = n0 + nb + u * 16 + g;
#pragma unroll
            for (int j = 0; j < NWS; ++j)
                wj[j][u] = __ldg(&d_ww[(size_t)j * Bz * Nz + bN + n]);
            if (L >= 1) wrv[u] = __ldg(&d_wr[(size_t)(L - 1) * Bz * Nz + bN + n]);
        }
        // ---- compute ----
#pragma unroll
        for (int u = 0; u < 4; ++u) {
            float4 vv = v[u];
            int n = n0 + nb + u * 16 + g;
            // chain writes 0..L-2:  v' = fma(w, fma(-e, v, a), v)
#pragma unroll
            for (int j = 0; j < NH; ++j) {
                if (j < L - 1) {
                    float w = wj[j][u];
                    vv.x = fmaf(w, fmaf(ne[j][0], vv.x, aa[j][0]), vv.x);
                    vv.y = fmaf(w, fmaf(ne[j][1], vv.y, aa[j][1]), vv.y);
                    vv.z = fmaf(w, fmaf(ne[j][2], vv.z, aa[j][2]), vv.z);
                    vv.w = fmaf(w, fmaf(ne[j][3], vv.w, aa[j][3]), vv.w);
                }
            }
            if (L >= 1) {
                float w = wrv[u];
                r0 = fmaf(w, vv.x, r0); r1 = fmaf(w, vv.y, r1);
                r2 = fmaf(w, vv.z, r2); r3 = fmaf(w, vv.w, r3);
                if (L <= 3) {
                    float wa = wj[JA][u];
                    vv.x = fmaf(wa, fmaf(ne[JA][0], vv.x, aa[JA][0]), vv.x);
                    vv.y = fmaf(wa, fmaf(ne[JA][1], vv.y, aa[JA][1]), vv.y);
                    vv.z = fmaf(wa, fmaf(ne[JA][2], vv.z, aa[JA][2]), vv.z);
                    vv.w = fmaf(wa, fmaf(ne[JA][3], vv.w, aa[JA][3]), vv.w);
                }
            }
            if (DOTS) {
                float pr = vv.x * kr[0] + vv.y * kr[1] + vv.z * kr[2] + vv.w * kr[3];
                float pn = vv.x * vv.x + vv.y * vv.y + vv.z * vv.z + vv.w * vv.w;
                float pw = 0.f;
                if (DOTW)
                    pw = vv.x * kw[0] + vv.y * kw[1] + vv.z * kw[2] + vv.w * kw[3];
#pragma unroll
                for (int off = 8; off; off >>= 1) {
                    pr += __shfl_down_sync(0xffffffffu, pr, off, 16);
                    pn += __shfl_down_sync(0xffffffffu, pn, off, 16);
                    if (DOTW) pw += __shfl_down_sync(0xffffffffu, pw, off, 16);
                }
                if (t == 0) {
                    d_dotr[bN + n] = pr;
                    d_rn[bN + n] = sqrtf(pn);
                    if (DOTW) d_dotw[bN + n] = pw;
                }
            }
        }
    }

    if (L >= 1) {
        red[g][tm + 0] = r0; red[g][tm + 1] = r1;
        red[g][tm + 2] = r2; red[g][tm + 3] = r3;
        __syncthreads();
        if (tid < 64) {
            float s = 0.f;
#pragma unroll
            for (int gg = 0; gg < 16; ++gg) s += red[gg][tid];
            d_readpart[(((L - 1) * NTILES + blockIdx.x) * Bz + b) * 64 + tid] = s;
        }
    }
}

// ---------------- addressing: softmax / interpolate / shift / sharpen --------
__global__ void weights_kernel(int pair, const float* __restrict__ prevw) {
    const int b = blockIdx.y;
    const int hsub = blockIdx.x;
    const int head = 2 * pair + hsub;
    const float* __restrict__ dot = hsub ? d_dotw : d_dotr;
    const int tid = threadIdx.x;    // 256
    __shared__ float wg_s[Nz];
    __shared__ float red[256];

    const size_t bN = (size_t)b * Nz;
    const float beta  = d_betaA[head * Bz + b];
    const float gate  = d_gateA[head * Bz + b];
    const float gamma = d_gammaA[head * Bz + b];
    const float s0 = d_shiftA[(head * Bz + b) * 3 + 0];
    const float s1 = d_shiftA[(head * Bz + b) * 3 + 1];
    const float s2 = d_shiftA[(head * Bz + b) * 3 + 2];
    const float kn = d_knorm[head * Bz + b];

    float lg[16];
    float lmax = -1e30f;
#pragma unroll
    for (int r = 0; r < 16; ++r) {
        int n = tid + r * 256;
        float l = __fdividef(beta * dot[bN + n], d_rn[bN + n] * kn + 1e-8f);
        lg[r] = l;
        lmax = fmaxf(lmax, l);
    }
    red[tid] = lmax; __syncthreads();
    for (int s = 128; s; s >>= 1) { if (tid < s) red[tid] = fmaxf(red[tid], red[tid + s]); __syncthreads(); }
    lmax = red[0]; __syncthreads();

    float esum = 0.f;
#pragma unroll
    for (int r = 0; r < 16; ++r) {
        float e = __expf(lg[r] - lmax);
        wg_s[tid + r * 256] = e;
        esum += e;
    }
    red[tid] = esum; __syncthreads();
    for (int s = 128; s; s >>= 1) { if (tid < s) red[tid] += red[tid + s]; __syncthreads(); }
    float inv = 1.f / red[0]; __syncthreads();

#pragma unroll
    for (int r = 0; r < 16; ++r) {
        int n = tid + r * 256;
        wg_s[n] = gate * (wg_s[n] * inv)
                + (1.f - gate) * prevw[(size_t)head * Bz * Nz + bN + n];
    }
    __syncthreads();

    float wp[16];
    float psum = 0.f;
#pragma unroll
    for (int r = 0; r < 16; ++r) {
        int n = tid + r * 256;
        float ws = s0 * wg_s[(n + Nz - 1) & (Nz - 1)]
                 + s1 * wg_s[n]
                 + s2 * wg_s[(n + 1) & (Nz - 1)];
        float p = __powf(ws, gamma);
        wp[r] = p;
        psum += p;
    }
    red[tid] = psum; __syncthreads();
    for (int s = 128; s; s >>= 1) { if (tid < s) red[tid] += red[tid + s]; __syncthreads(); }
    float invp = 1.f / (red[0] + 1e-8f);

    float* __restrict__ wout = hsub ? (d_ww + (size_t)pair * Bz * Nz)
                                    : (d_wr + (size_t)pair * Bz * Nz);
#pragma unroll
    for (int r = 0; r < 16; ++r) {
        int n = tid + r * 256;
        wout[bN + n] = wp[r] * invp;
    }
}

// ---------------- finalize reads ---------------------------------------------
__global__ void reduce_reads() {
    int idx = blockIdx.x * 256 + threadIdx.x;   // 4*Bz*64
    if (idx >= 4 * Bz * 64) return;
    int i = idx / (Bz * 64), rem = idx - i * (Bz * 64);
    float s = 0.f;
#pragma unroll
    for (int t = 0; t < NTILES; ++t)
        s += d_readpart[(i * NTILES + t) * (Bz * 64) + rem];
    d_reads[idx] = s;
}

// ---------------- output layer -----------------------------------------------
__global__ void out_kernel(const float* __restrict__ Wout,
                           const float* __restrict__ bout,
                           float* __restrict__ out) {
    int b = blockIdx.x, o = threadIdx.x;    // 64 threads
    const float* wrow = Wout + (size_t)o * 768;
    const float* hh = d_hst + (size_t)b * Cz;
    float a0 = 0.f, a1 = 0.f, a2 = 0.f, a3 = 0.f;
    for (int k = 0; k < 512; k += 4) {
        a0 += hh[k] * wrow[k];         a1 += hh[k + 1] * wrow[k + 1];
        a2 += hh[k + 2] * wrow[k + 2]; a3 += hh[k + 3] * wrow[k + 3];
    }
#pragma unroll
    for (int i = 0; i < 4; ++i) {
        const float* rr = d_reads + (size_t)(i * Bz + b) * 64;
        const float* w2 = wrow + 512 + i * 64;
        for (int m = 0; m < 64; m += 4) {
            a0 += rr[m] * w2[m];           a1 += rr[m + 1] * w2[m + 1];
            a2 += rr[m + 2] * w2[m + 2];   a3 += rr[m + 3] * w2[m + 3];
        }
    }
    float s = a0 + a1 + a2 + a3 + bout[o];
    out[(size_t)b * 64 + o] = 1.f / (1.f + __expf(-s));
}

// ---------------- launch -----------------------------------------------------
extern "C" void kernel_launch(void* const* d_in, const int* in_sizes, int n_in,
                              void* d_out, int out_size) {
    const float* in_data = (const float*)d_in[0];
    const float* memory  = (const float*)d_in[1];
    const float* h0      = (const float*)d_in[2];
    const float* c0      = (const float*)d_in[3];
    const float* prevw   = (const float*)d_in[4];
    const float* prevr   = (const float*)d_in[5];
    const float* W_ih    = (const float*)d_in[6];
    const float* b_ih    = (const float*)d_in[7];
    const float* W_hh    = (const float*)d_in[8];
    const float* b_hh    = (const float*)d_in[9];
    const float* W_out   = (const float*)d_in[10];
    const float* b_out   = (const float*)d_in[11];
    const float* W_addr  = (const float*)d_in[12];
    const float* b_addr  = (const float*)d_in[13];
    const float* W_ea    = (const float*)d_in[14];
    const float* b_ea    = (const float*)d_in[15];
    float* out = (float*)d_out;

    gemm_gates<<<dim3(G4 / 64, Bz / 64, 2), 256>>>(W_ih, W_hh, in_data, prevr, h0);
    lstm_act<<<Bz * Cz / 256, 256>>>(c0, b_ih, b_hh);
    gemm_addr<<<dim3((PN + 63) / 64, Bz / 64, 8), 256>>>(W_addr, W_ea);

    pass_kernel<0><<<dim3(NTILES, Bz), 256>>>(memory, b_addr);   // 4th launch -> profiled
    head_params<<<dim3(8, Bz), 64>>>(b_addr, b_ea);
    weights_kernel<<<dim3(2, Bz), 256>>>(0, prevw);
    pass_kernel<1><<<dim3(NTILES, Bz), 256>>>(memory, b_addr);
    weights_kernel<<<dim3(2, Bz), 256>>>(1, prevw);
    pass_kernel<2><<<dim3(NTILES, Bz), 256>>>(memory, b_addr);
    weights_kernel<<<dim3(2, Bz), 256>>>(2, prevw);
    pass_kernel<3><<<dim3(NTILES, Bz), 256>>>(memory, b_addr);
    weights_kernel<<<dim3(1, Bz), 256>>>(3, prevw);   // head 6 only; head 7 write is dead
    pass_kernel<4><<<dim3(NTILES, Bz), 256>>>(memory, b_addr);

    reduce_reads<<<(4 * Bz * 64 + 255) / 256, 256>>>();
    out_kernel<<<Bz, 64>>>(W_out, b_out, out);
}

// round 13
// speedup vs baseline: 1.3430x; 1.3430x over previous
#include <cuda_runtime.h>

#define Bz 256
#define Nz 4096
#define Mz 64
#define Cz 512
#define G4 2048
#define Kcat 832     // IN(64) + H*M(256) + C(512)
#define PN 560       // 8 * 70
#define EAN 512      // 4 * 128
#define NTILES 16    // Nz / 256

// ---------------- scratch (static device globals; no allocation) -------------
__device__ float d_gatesP[2 * (size_t)Bz * G4];   // 2 K-splits
__device__ float d_PpP[4 * (size_t)Bz * PN];      // 4 K-splits
__device__ float d_EApP[4 * (size_t)Bz * EAN];
__device__ float d_cst[Bz * Cz];
__device__ float d_hst[Bz * Cz];
__device__ float d_key[8 * Bz * Mz];
__device__ float d_knorm[8 * Bz];
__device__ float d_betaA[8 * Bz];
__device__ float d_gateA[8 * Bz];
__device__ float d_gammaA[8 * Bz];
__device__ float d_shiftA[8 * Bz * 3];
__device__ float d_eA[4 * Bz * Mz];
__device__ float d_aA[4 * Bz * Mz];
__device__ float d_dotr[(size_t)Bz * Nz];
__device__ float d_dotw[(size_t)Bz * Nz];
__device__ float d_rn[(size_t)Bz * Nz];
__device__ float d_ww[3 * (size_t)Bz * Nz];   // write weights, pairs 0..2 (pair3 write is dead)
__device__ float d_wr[4 * (size_t)Bz * Nz];   // read weights, pairs 0..3
__device__ float d_readpart[4 * NTILES * Bz * Mz];
__device__ float d_reads[4 * Bz * Mz];

// ---------------- helpers ----------------------------------------------------
__device__ __forceinline__ float sigm(float x) { return 1.f / (1.f + __expf(-x)); }
__device__ __forceinline__ float softplusf(float x) {
    return (x > 20.f) ? x : log1pf(__expf(x));
}

// ---------------- gates GEMM (xcat assembled on the fly, K-split 2) ----------
__global__ void gemm_gates(const float* __restrict__ W_ih,
                           const float* __restrict__ W_hh,
                           const float* __restrict__ in_data,
                           const float* __restrict__ prev_reads,
                           const float* __restrict__ h0) {
    __shared__ float As[16][64];
    __shared__ float Ws[16][64];
    int tid = threadIdx.x;
    int tx = tid & 15, ty = tid >> 4;
    int m0 = blockIdx.y * 64;
    int j0 = blockIdx.x * 64;
    int z = blockIdx.z;                 // K-split 0/1
    int kbeg = z * 416, kend = kbeg + 416;
    int lrow = tid >> 2;
    int lk4 = (tid & 3) * 4;

    float acc[4][4] = {};
    for (int k0 = kbeg; k0 < kend; k0 += 16) {
        int m = m0 + lrow;
        int k = k0 + lk4;
        float4 av;
        if (k < 64) {
            av = *(const float4*)&in_data[m * 64 + k];
        } else if (k < 320) {
            int i = (k - 64) >> 6, mm = (k - 64) & 63;
            av = *(const float4*)&prev_reads[(i * Bz + m) * 64 + mm];
        } else {
            av = *(const float4*)&h0[m * Cz + (k - 320)];
        }
        As[lk4 + 0][lrow] = av.x; As[lk4 + 1][lrow] = av.y;
        As[lk4 + 2][lrow] = av.z; As[lk4 + 3][lrow] = av.w;
        int j = j0 + lrow;
        const float* src; int kl;
        if (k0 < 320) { src = W_ih + (size_t)j * 320; kl = k0; }
        else          { src = W_hh + (size_t)j * 512; kl = k0 - 320; }
        float4 wv = *(const float4*)&src[kl + lk4];
        Ws[lk4 + 0][lrow] = wv.x; Ws[lk4 + 1][lrow] = wv.y;
        Ws[lk4 + 2][lrow] = wv.z; Ws[lk4 + 3][lrow] = wv.w;
        __syncthreads();
#pragma unroll
        for (int kk = 0; kk < 16; ++kk) {
            float4 a4 = *(const float4*)&As[kk][ty * 4];
            float4 w4 = *(const float4*)&Ws[kk][tx * 4];
            acc[0][0] += a4.x * w4.x; acc[0][1] += a4.x * w4.y;
            acc[0][2] += a4.x * w4.z; acc[0][3] += a4.x * w4.w;
            acc[1][0] += a4.y * w4.x; acc[1][1] += a4.y * w4.y;
            acc[1][2] += a4.y * w4.z; acc[1][3] += a4.y * w4.w;
            acc[2][0] += a4.z * w4.x; acc[2][1] += a4.z * w4.y;
            acc[2][2] += a4.z * w4.z; acc[2][3] += a4.z * w4.w;
            acc[3][0] += a4.w * w4.x; acc[3][1] += a4.w * w4.y;
            acc[3][2] += a4.w * w4.z; acc[3][3] += a4.w * w4.w;
        }
        __syncthreads();
    }
    float* out = d_gatesP + (size_t)z * Bz * G4;
#pragma unroll
    for (int i = 0; i < 4; ++i) {
        int m = m0 + ty * 4 + i;
#pragma unroll
        for (int jj = 0; jj < 4; ++jj)
            out[(size_t)m * G4 + j0 + tx * 4 + jj] = acc[i][jj];
    }
}

// ---------------- addressing GEMMs (P + EA, K-split 4) ------------------------
__global__ void gemm_addr(const float* __restrict__ W_addr,
                          const float* __restrict__ W_ea) {
    int z = blockIdx.z;
    int tgt = z >> 2, ks = z & 3;
    if (tgt == 1 && blockIdx.x >= EAN / 64) return;
    const float* W = tgt ? W_ea : W_addr;
    int Nc = tgt ? EAN : PN;
    float* out = tgt ? (d_EApP + (size_t)ks * Bz * EAN)
                     : (d_PpP + (size_t)ks * Bz * PN);
    int kbeg = ks * 128, kend = kbeg + 128;

    __shared__ float As[16][64];
    __shared__ float Ws[16][64];
    int tid = threadIdx.x;
    int tx = tid & 15, ty = tid >> 4;
    int m0 = blockIdx.y * 64;
    int j0 = blockIdx.x * 64;
    int lrow = tid >> 2;
    int lk4 = (tid & 3) * 4;

    float acc[4][4] = {};
    for (int k0 = kbeg; k0 < kend; k0 += 16) {
        float4 av = *(const float4*)&d_cst[(size_t)(m0 + lrow) * Cz + k0 + lk4];
        As[lk4 + 0][lrow] = av.x; As[lk4 + 1][lrow] = av.y;
        As[lk4 + 2][lrow] = av.z; As[lk4 + 3][lrow] = av.w;
        int j = j0 + lrow;
        float4 wv = make_float4(0.f, 0.f, 0.f, 0.f);
        if (j < Nc) wv = *(const float4*)&W[(size_t)j * Cz + k0 + lk4];
        Ws[lk4 + 0][lrow] = wv.x; Ws[lk4 + 1][lrow] = wv.y;
        Ws[lk4 + 2][lrow] = wv.z; Ws[lk4 + 3][lrow] = wv.w;
        __syncthreads();
#pragma unroll
        for (int kk = 0; kk < 16; ++kk) {
            float4 a4 = *(const float4*)&As[kk][ty * 4];
            float4 w4 = *(const float4*)&Ws[kk][tx * 4];
            acc[0][0] += a4.x * w4.x; acc[0][1] += a4.x * w4.y;
            acc[0][2] += a4.x * w4.z; acc[0][3] += a4.x * w4.w;
            acc[1][0] += a4.y * w4.x; acc[1][1] += a4.y * w4.y;
            acc[1][2] += a4.y * w4.z; acc[1][3] += a4.y * w4.w;
            acc[2][0] += a4.z * w4.x; acc[2][1] += a4.z * w4.y;
            acc[2][2] += a4.z * w4.z; acc[2][3] += a4.z * w4.w;
            acc[3][0] += a4.w * w4.x; acc[3][1] += a4.w * w4.y;
            acc[3][2] += a4.w * w4.z; acc[3][3] += a4.w * w4.w;
        }
        __syncthreads();
    }
#pragma unroll
    for (int i = 0; i < 4; ++i) {
        int m = m0 + ty * 4 + i;
#pragma unroll
        for (int jj = 0; jj < 4; ++jj) {
            int j = j0 + tx * 4 + jj;
            if (j < Nc) out[(size_t)m * Nc + j] = acc[i][jj];
        }
    }
}

// ---------------- LSTM activations (sums K-split partials + bias) -------------
__global__ void lstm_act(const float* __restrict__ c0,
                         const float* __restrict__ b_ih,
                         const float* __restrict__ b_hh) {
    int idx = blockIdx.x * 256 + threadIdx.x;   // Bz*Cz
    int b = idx >> 9, j = idx & 511;
    const size_t off2 = (size_t)Bz * G4;
    const float* g0 = d_gatesP + (size_t)b * G4;
    const float* g1 = d_gatesP + off2 + (size_t)b * G4;
    float ig = g0[j]        + g1[j]        + b_ih[j]        + b_hh[j];
    float fg = g0[512 + j]  + g1[512 + j]  + b_ih[512 + j]  + b_hh[512 + j];
    float gg = g0[1024 + j] + g1[1024 + j] + b_ih[1024 + j] + b_hh[1024 + j];
    float og = g0[1536 + j] + g1[1536 + j] + b_ih[1536 + j] + b_hh[1536 + j];
    float c = sigm(fg) * c0[idx] + sigm(ig) * tanhf(gg);
    d_cst[idx] = c;
    d_hst[idx] = sigm(og) * tanhf(c);
}

// ---------------- per-head derived parameters (sums K-split partials) ---------
// Runs AFTER pass0 (which computes its own pair-0 keys from d_PpP directly).
__global__ void head_params(const float* __restrict__ b_addr,
                            const float* __restrict__ b_ea) {
    int hi = blockIdx.x, b = blockIdx.y, m = threadIdx.x;   // 64 threads
    __shared__ float sm[64];

    float pv = b_addr[hi * 70 + m];
#pragma unroll
    for (int s = 0; s < 4; ++s)
        pv += d_PpP[(size_t)s * Bz * PN + (size_t)b * PN + hi * 70 + m];
    float k = tanhf(pv);
    d_key[(hi * Bz + b) * 64 + m] = k;
    sm[m] = k * k;
    __syncthreads();
    for (int s = 32; s; s >>= 1) { if (m < s) sm[m] += sm[m + s]; __syncthreads(); }
    if (m == 0) {
        float tail[6];
#pragma unroll
        for (int t = 0; t < 6; ++t) {
            float v = b_addr[hi * 70 + 64 + t];
#pragma unroll
            for (int s = 0; s < 4; ++s)
                v += d_PpP[(size_t)s * Bz * PN + (size_t)b * PN + hi * 70 + 64 + t];
            tail[t] = v;
        }
        d_knorm[hi * Bz + b] = sqrtf(sm[0]);
        d_betaA[hi * Bz + b] = softplusf(tail[0]);
        d_gateA[hi * Bz + b] = sigm(tail[1]);
        float a0 = tail[2], a1 = tail[3], a2 = tail[4];
        float mx = fmaxf(a0, fmaxf(a1, a2));
        float e0 = __expf(a0 - mx), e1 = __expf(a1 - mx), e2 = __expf(a2 - mx);
        float is = 1.f / (e0 + e1 + e2);
        d_shiftA[(hi * Bz + b) * 3 + 0] = e0 * is;
        d_shiftA[(hi * Bz + b) * 3 + 1] = e1 * is;
        d_shiftA[(hi * Bz + b) * 3 + 2] = e2 * is;
        d_gammaA[hi * Bz + b] = 1.f + softplusf(tail[5]);
    }
    if (hi < 4) {
        float e = b_ea[hi * 128 + m];
        float a = b_ea[hi * 128 + 64 + m];
#pragma unroll
        for (int s = 0; s < 4; ++s) {
            e += d_EApP[(size_t)s * Bz * EAN + (size_t)b * EAN + hi * 128 + m];
            a += d_EApP[(size_t)s * Bz * EAN + (size_t)b * EAN + hi * 128 + 64 + m];
        }
        d_eA[(hi * Bz + b) * 64 + m] = sigm(e);
        d_aA[(hi * Bz + b) * 64 + m] = tanhf(a);
    }
}

// ---------------- big memory passes (scalar FMA) -------------------------------
// Pass L: recompute chain of writes 0..L-2 from mem0; read with wr[L-1];
// apply write L-1; dots for pair L (skip write-head dot at L==3; none at L==4).
// Pass 0: occ 4 (measured 44 regs, 73.7us). Passes 1-4: occ 2 (128-reg cap, no spill).
template <int L>
__global__ void __launch_bounds__(256, (L == 0) ? 4 : 2)
pass_kernel(const float* __restrict__ mem0, const float* __restrict__ b_addr) {
    const int b = blockIdx.y;
    const int n0 = blockIdx.x * 256;
    const int tid = threadIdx.x;
    const int g = tid >> 4, t = tid & 15;
    const int tm = t * 4;
    const size_t bN = (size_t)b * Nz;

    __shared__ float e_s[3][64], a_s[3][64];
    __shared__ float kr_s[64], kw_s[64];
    __shared__ float red[16][64];

    constexpr int NH  = (L < 3) ? L : 3;         // e/a vectors 0..NH-1
    constexpr int NWS = (L < 3) ? L : 3;         // ww streams read
    constexpr bool DOTS = (L <= 3);
    constexpr bool DOTW = (L < 3);
    constexpr int JA = (L >= 1) ? (L - 1) : 0;   // applied write index

    for (int idx = tid; idx < NH * 64; idx += 256) {
        int j = idx >> 6, m = idx & 63;
        e_s[j][m] = d_eA[(j * Bz + b) * 64 + m];
        a_s[j][m] = d_aA[(j * Bz + b) * 64 + m];
    }
    if (L == 0) {
        // self-compute pair-0 keys from GEMM partials (head_params not yet run)
        if (tid < 128) {
            int hi = tid >> 6, m = tid & 63;
            float pv = b_addr[hi * 70 + m];
#pragma unroll
            for (int s = 0; s < 4; ++s)
                pv += d_PpP[(size_t)s * Bz * PN + (size_t)b * PN + hi * 70 + m];
            float k = tanhf(pv);
            if (hi == 0) kr_s[m] = k; else kw_s[m] = k;
        }
    } else if (DOTS) {
        if (tid < 64) kr_s[tid] = d_key[((2 * L) * Bz + b) * 64 + tid];
        else if (DOTW && tid < 128)
            kw_s[tid - 64] = d_key[((2 * L + 1) * Bz + b) * 64 + (tid - 64)];
    }
    __syncthreads();

    // hoist per-column params to registers (scalar)
    float ne[NH > 0 ? NH : 1][4], aa[NH > 0 ? NH : 1][4];
#pragma unroll
    for (int j = 0; j < NH; ++j)
#pragma unroll
        for (int x = 0; x < 4; ++x) {
            ne[j][x] = -e_s[j][tm + x];
            aa[j][x] =  a_s[j][tm + x];
        }
    float kr[4] = {}, kw[4] = {};
    if (DOTS) {
#pragma unroll
        for (int x = 0; x < 4; ++x) kr[x] = kr_s[tm + x];
        if (DOTW)
#pragma unroll
            for (int x = 0; x < 4; ++x) kw[x] = kw_s[tm + x];
    }

    float r0 = 0.f, r1 = 0.f, r2 = 0.f, r3 = 0.f;
    const float* base = mem0 + (((size_t)(bN + n0)) << 6);

#pragma unroll
    for (int rr = 0; rr < 4; ++rr) {
        const int nb = rr * 64;
        float4 v[4];
        float wj[NWS > 0 ? NWS : 1][4];
        float wrv[4];
        // ---- batch ALL global loads first (MLP >= 4) ----
#pragma unroll
        for (int u = 0; u < 4; ++u) {
            int row = nb + u * 16 + g;
            v[u] = *(const float4*)(base + (((size_t)row) << 6) + tm);
        }
#pragma unroll
        for (int u = 0; u < 4; ++u) {
            int n = n0 + nb + u * 16 + g;
#pragma unroll
            for (int j = 0; j < NWS; ++j)
                wj[j][u] = __ldg(&d_ww[(size_t)j * Bz * Nz + bN + n]);
            if (L >= 1) wrv[u] = __ldg(&d_wr[(size_t)(L - 1) * Bz * Nz + bN + n]);
        }
        // ---- compute ----
#pragma unroll
        for (int u = 0; u < 4; ++u) {
            float4 vv = v[u];
            int n = n0 + nb + u * 16 + g;
            // chain writes 0..L-2:  v' = fma(w, fma(-e, v, a), v)
#pragma unroll
            for (int j = 0; j < NH; ++j) {
                if (j < L - 1) {
                    float w = wj[j][u];
                    vv.x = fmaf(w, fmaf(ne[j][0], vv.x, aa[j][0]), vv.x);
                    vv.y = fmaf(w, fmaf(ne[j][1], vv.y, aa[j][1]), vv.y);
                    vv.z = fmaf(w, fmaf(ne[j][2], vv.z, aa[j][2]), vv.z);
                    vv.w = fmaf(w, fmaf(ne[j][3], vv.w, aa[j][3]), vv.w);
                }
            }
            if (L >= 1) {
                float w = wrv[u];
                r0 = fmaf(w, vv.x, r0); r1 = fmaf(w, vv.y, r1);
                r2 = fmaf(w, vv.z, r2); r3 = fmaf(w, vv.w, r3);
                if (L <= 3) {
                    float wa = wj[JA][u];
                    vv.x = fmaf(wa, fmaf(ne[JA][0], vv.x, aa[JA][0]), vv.x);
                    vv.y = fmaf(wa, fmaf(ne[JA][1], vv.y, aa[JA][1]), vv.y);
                    vv.z = fmaf(wa, fmaf(ne[JA][2], vv.z, aa[JA][2]), vv.z);
                    vv.w = fmaf(wa, fmaf(ne[JA][3], vv.w, aa[JA][3]), vv.w);
                }
            }
            if (DOTS) {
                float pr = vv.x * kr[0] + vv.y * kr[1] + vv.z * kr[2] + vv.w * kr[3];
                float pn = vv.x * vv.x + vv.y * vv.y + vv.z * vv.z + vv.w * vv.w;
                float pw = 0.f;
                if (DOTW)
                    pw = vv.x * kw[0] + vv.y * kw[1] + vv.z * kw[2] + vv.w * kw[3];
#pragma unroll
                for (int off = 8; off; off >>= 1) {
                    pr += __shfl_down_sync(0xffffffffu, pr, off, 16);
                    pn += __shfl_down_sync(0xffffffffu, pn, off, 16);
                    if (DOTW) pw += __shfl_down_sync(0xffffffffu, pw, off, 16);
                }
                if (t == 0) {
                    d_dotr[bN + n] = pr;
                    d_rn[bN + n] = sqrtf(pn);
                    if (DOTW) d_dotw[bN + n] = pw;
                }
            }
        }
    }

    if (L >= 1) {
        red[g][tm + 0] = r0; red[g][tm + 1] = r1;
        red[g][tm + 2] = r2; red[g][tm + 3] = r3;
        __syncthreads();
        if (tid < 64) {
            float s = 0.f;
#pragma unroll
            for (int gg = 0; gg < 16; ++gg) s += red[gg][tid];
            d_readpart[(((L - 1) * NTILES + blockIdx.x) * Bz + b) * 64 + tid] = s;
        }
    }
}

// ---------------- addressing: softmax / interpolate / shift / sharpen --------
__global__ void weights_kernel(int pair, const float* __restrict__ prevw) {
    const int b = blockIdx.y;
    const int hsub = blockIdx.x;
    const int head = 2 * pair + hsub;
    const float* __restrict__ dot = hsub ? d_dotw : d_dotr;
    const int tid = threadIdx.x;    // 256
    __shared__ float wg_s[Nz];
    __shared__ float red[256];

    const size_t bN = (size_t)b * Nz;
    const float beta  = d_betaA[head * Bz + b];
    const float gate  = d_gateA[head * Bz + b];
    const float gamma = d_gammaA[head * Bz + b];
    const float s0 = d_shiftA[(head * Bz + b) * 3 + 0];
    const float s1 = d_shiftA[(head * Bz + b) * 3 + 1];
    const float s2 = d_shiftA[(head * Bz + b) * 3 + 2];
    const float kn = d_knorm[head * Bz + b];

    float lg[16];
    float lmax = -1e30f;
#pragma unroll
    for (int r = 0; r < 16; ++r) {
        int n = tid + r * 256;
        float l = __fdividef(beta * dot[bN + n], d_rn[bN + n] * kn + 1e-8f);
        lg[r] = l;
        lmax = fmaxf(lmax, l);
    }
    red[tid] = lmax; __syncthreads();
    for (int s = 128; s; s >>= 1) { if (tid < s) red[tid] = fmaxf(red[tid], red[tid + s]); __syncthreads(); }
    lmax = red[0]; __syncthreads();

    float esum = 0.f;
#pragma unroll
    for (int r = 0; r < 16; ++r) {
        float e = __expf(lg[r] - lmax);
        wg_s[tid + r * 256] = e;
        esum += e;
    }
    red[tid] = esum; __syncthreads();
    for (int s = 128; s; s >>= 1) { if (tid < s) red[tid] += red[tid + s]; __syncthreads(); }
    float inv = 1.f / red[0]; __syncthreads();

#pragma unroll
    for (int r = 0; r < 16; ++r) {
        int n = tid + r * 256;
        wg_s[n] = gate * (wg_s[n] * inv)
                + (1.f - gate) * prevw[(size_t)head * Bz * Nz + bN + n];
    }
    __syncthreads();

    float wp[16];
    float psum = 0.f;
#pragma unroll
    for (int r = 0; r < 16; ++r) {
        int n = tid + r * 256;
        float ws = s0 * wg_s[(n + Nz - 1) & (Nz - 1)]
                 + s1 * wg_s[n]
                 + s2 * wg_s[(n + 1) & (Nz - 1)];
        float p = __powf(ws, gamma);
        wp[r] = p;
        psum += p;
    }
    red[tid] = psum; __syncthreads();
    for (int s = 128; s; s >>= 1) { if (tid < s) red[tid] += red[tid + s]; __syncthreads(); }
    float invp = 1.f / (red[0] + 1e-8f);

    float* __restrict__ wout = hsub ? (d_ww + (size_t)pair * Bz * Nz)
                                    : (d_wr + (size_t)pair * Bz * Nz);
#pragma unroll
    for (int r = 0; r < 16; ++r) {
        int n = tid + r * 256;
        wout[bN + n] = wp[r] * invp;
    }
}

// ---------------- finalize reads ---------------------------------------------
__global__ void reduce_reads() {
    int idx = blockIdx.x * 256 + threadIdx.x;   // 4*Bz*64
    if (idx >= 4 * Bz * 64) return;
    int i = idx / (Bz * 64), rem = idx - i * (Bz * 64);
    float s = 0.f;
#pragma unroll
    for (int t = 0; t < NTILES; ++t)
        s += d_readpart[(i * NTILES + t) * (Bz * 64) + rem];
    d_reads[idx] = s;
}

// ---------------- output layer -----------------------------------------------
__global__ void out_kernel(const float* __restrict__ Wout,
                           const float* __restrict__ bout,
                           float* __restrict__ out) {
    int b = blockIdx.x, o = threadIdx.x;    // 64 threads
    const float* wrow = Wout + (size_t)o * 768;
    const float* hh = d_hst + (size_t)b * Cz;
    float a0 = 0.f, a1 = 0.f, a2 = 0.f, a3 = 0.f;
    for (int k = 0; k < 512; k += 4) {
        a0 += hh[k] * wrow[k];         a1 += hh[k + 1] * wrow[k + 1];
        a2 += hh[k + 2] * wrow[k + 2]; a3 += hh[k + 3] * wrow[k + 3];
    }
#pragma unroll
    for (int i = 0; i < 4; ++i) {
        const float* rr = d_reads + (size_t)(i * Bz + b) * 64;
        const float* w2 = wrow + 512 + i * 64;
        for (int m = 0; m < 64; m += 4) {
            a0 += rr[m] * w2[m];           a1 += rr[m + 1] * w2[m + 1];
            a2 += rr[m + 2] * w2[m + 2];   a3 += rr[m + 3] * w2[m + 3];
        }
    }
    float s = a0 + a1 + a2 + a3 + bout[o];
    out[(size_t)b * 64 + o] = 1.f / (1.f + __expf(-s));
}

// ---------------- launch -----------------------------------------------------
extern "C" void kernel_launch(void* const* d_in, const int* in_sizes, int n_in,
                              void* d_out, int out_size) {
    const float* in_data = (const float*)d_in[0];
    const float* memory  = (const float*)d_in[1];
    const float* h0      = (const float*)d_in[2];
    const float* c0      = (const float*)d_in[3];
    const float* prevw   = (const float*)d_in[4];
    const float* prevr   = (const float*)d_in[5];
    const float* W_ih    = (const float*)d_in[6];
    const float* b_ih    = (const float*)d_in[7];
    const float* W_hh    = (const float*)d_in[8];
    const float* b_hh    = (const float*)d_in[9];
    const float* W_out   = (const float*)d_in[10];
    const float* b_out   = (const float*)d_in[11];
    const float* W_addr  = (const float*)d_in[12];
    const float* b_addr  = (const float*)d_in[13];
    const float* W_ea    = (const float*)d_in[14];
    const float* b_ea    = (const float*)d_in[15];
    float* out = (float*)d_out;

    gemm_gates<<<dim3(G4 / 64, Bz / 64, 2), 256>>>(W_ih, W_hh, in_data, prevr, h0);
    lstm_act<<<Bz * Cz / 256, 256>>>(c0, b_ih, b_hh);
    gemm_addr<<<dim3((PN + 63) / 64, Bz / 64, 8), 256>>>(W_addr, W_ea);

    pass_kernel<0><<<dim3(NTILES, Bz), 256>>>(memory, b_addr);   // 4th launch -> profiled
    head_params<<<dim3(8, Bz), 64>>>(b_addr, b_ea);
    weights_kernel<<<dim3(2, Bz), 256>>>(0, prevw);
    pass_kernel<1><<<dim3(NTILES, Bz), 256>>>(memory, b_addr);
    weights_kernel<<<dim3(2, Bz), 256>>>(1, prevw);
    pass_kernel<2><<<dim3(NTILES, Bz), 256>>>(memory, b_addr);
    weights_kernel<<<dim3(2, Bz), 256>>>(2, prevw);
    pass_kernel<3><<<dim3(NTILES, Bz), 256>>>(memory, b_addr);
    weights_kernel<<<dim3(1, Bz), 256>>>(3, prevw);   // head 6 only; head 7 write is dead
    pass_kernel<4><<<dim3(NTILES, Bz), 256>>>(memory, b_addr);

    reduce_reads<<<(4 * Bz * 64 + 255) / 256, 256>>>();
    out_kernel<<<Bz, 64>>>(W_out, b_out, out);
}

// round 16
// speedup vs baseline: 1.3542x; 1.0084x over previous
#include <cuda_runtime.h>

#define Bz 256
#define Nz 4096
#define Mz 64
#define Cz 512
#define G4 2048
#define Kcat 832     // IN(64) + H*M(256) + C(512)
#define PN 560       // 8 * 70
#define EAN 512      // 4 * 128
#define NTILES 16    // Nz / 256

// ---------------- scratch (static device globals; no allocation) -------------
__device__ float d_gatesP[2 * (size_t)Bz * G4];   // 2 K-splits
__device__ float d_PpP[4 * (size_t)Bz * PN];      // 4 K-splits
__device__ float d_EApP[4 * (size_t)Bz * EAN];
__device__ float d_cst[Bz * Cz];
__device__ float d_hst[Bz * Cz];
__device__ float d_key[8 * Bz * Mz];
__device__ float d_knorm[8 * Bz];
__device__ float d_betaA[8 * Bz];
__device__ float d_gateA[8 * Bz];
__device__ float d_gammaA[8 * Bz];
__device__ float d_shiftA[8 * Bz * 3];
__device__ float d_eA[4 * Bz * Mz];
__device__ float d_aA[4 * Bz * Mz];
__device__ float d_dotr[(size_t)Bz * Nz];
__device__ float d_dotw[(size_t)Bz * Nz];
__device__ float d_rn[(size_t)Bz * Nz];
__device__ float d_ww[3 * (size_t)Bz * Nz];   // write weights, pairs 0..2 (pair3 write is dead)
__device__ float d_wr[4 * (size_t)Bz * Nz];   // read weights, pairs 0..3
__device__ float d_readpart[4 * NTILES * Bz * Mz];
__device__ float d_reads[4 * Bz * Mz];

// ---------------- helpers ----------------------------------------------------
__device__ __forceinline__ float sigm(float x) { return 1.f / (1.f + __expf(-x)); }
__device__ __forceinline__ float softplusf(float x) {
    return (x > 20.f) ? x : log1pf(__expf(x));
}

// ---------------- gates GEMM (xcat assembled on the fly, K-split 2) ----------
__global__ void gemm_gates(const float* __restrict__ W_ih,
                           const float* __restrict__ W_hh,
                           const float* __restrict__ in_data,
                           const float* __restrict__ prev_reads,
                           const float* __restrict__ h0) {
    __shared__ float As[16][64];
    __shared__ float Ws[16][64];
    int tid = threadIdx.x;
    int tx = tid & 15, ty = tid >> 4;
    int m0 = blockIdx.y * 64;
    int j0 = blockIdx.x * 64;
    int z = blockIdx.z;                 // K-split 0/1
    int kbeg = z * 416, kend = kbeg + 416;
    int lrow = tid >> 2;
    int lk4 = (tid & 3) * 4;

    float acc[4][4] = {};
    for (int k0 = kbeg; k0 < kend; k0 += 16) {
        int m = m0 + lrow;
        int k = k0 + lk4;
        float4 av;
        if (k < 64) {
            av = *(const float4*)&in_data[m * 64 + k];
        } else if (k < 320) {
            int i = (k - 64) >> 6, mm = (k - 64) & 63;
            av = *(const float4*)&prev_reads[(i * Bz + m) * 64 + mm];
        } else {
            av = *(const float4*)&h0[m * Cz + (k - 320)];
        }
        As[lk4 + 0][lrow] = av.x; As[lk4 + 1][lrow] = av.y;
        As[lk4 + 2][lrow] = av.z; As[lk4 + 3][lrow] = av.w;
        int j = j0 + lrow;
        const float* src; int kl;
        if (k0 < 320) { src = W_ih + (size_t)j * 320; kl = k0; }
        else          { src = W_hh + (size_t)j * 512; kl = k0 - 320; }
        float4 wv = *(const float4*)&src[kl + lk4];
        Ws[lk4 + 0][lrow] = wv.x; Ws[lk4 + 1][lrow] = wv.y;
        Ws[lk4 + 2][lrow] = wv.z; Ws[lk4 + 3][lrow] = wv.w;
        __syncthreads();
#pragma unroll
        for (int kk = 0; kk < 16; ++kk) {
            float4 a4 = *(const float4*)&As[kk][ty * 4];
            float4 w4 = *(const float4*)&Ws[kk][tx * 4];
            acc[0][0] += a4.x * w4.x; acc[0][1] += a4.x * w4.y;
            acc[0][2] += a4.x * w4.z; acc[0][3] += a4.x * w4.w;
            acc[1][0] += a4.y * w4.x; acc[1][1] += a4.y * w4.y;
            acc[1][2] += a4.y * w4.z; acc[1][3] += a4.y * w4.w;
            acc[2][0] += a4.z * w4.x; acc[2][1] += a4.z * w4.y;
            acc[2][2] += a4.z * w4.z; acc[2][3] += a4.z * w4.w;
            acc[3][0] += a4.w * w4.x; acc[3][1] += a4.w * w4.y;
            acc[3][2] += a4.w * w4.z; acc[3][3] += a4.w * w4.w;
        }
        __syncthreads();
    }
    float* out = d_gatesP + (size_t)z * Bz * G4;
#pragma unroll
    for (int i = 0; i < 4; ++i) {
        int m = m0 + ty * 4 + i;
#pragma unroll
        for (int jj = 0; jj < 4; ++jj)
            out[(size_t)m * G4 + j0 + tx * 4 + jj] = acc[i][jj];
    }
}

// ---------------- addressing GEMMs (P + EA, K-split 4) ------------------------
__global__ void gemm_addr(const float* __restrict__ W_addr,
                          const float* __restrict__ W_ea) {
    int z = blockIdx.z;
    int tgt = z >> 2, ks = z & 3;
    if (tgt == 1 && blockIdx.x >= EAN / 64) return;
    const float* W = tgt ? W_ea : W_addr;
    int Nc = tgt ? EAN : PN;
    float* out = tgt ? (d_EApP + (size_t)ks * Bz * EAN)
                     : (d_PpP + (size_t)ks * Bz * PN);
    int kbeg = ks * 128, kend = kbeg + 128;

    __shared__ float As[16][64];
    __shared__ float Ws[16][64];
    int tid = threadIdx.x;
    int tx = tid & 15, ty = tid >> 4;
    int m0 = blockIdx.y * 64;
    int j0 = blockIdx.x * 64;
    int lrow = tid >> 2;
    int lk4 = (tid & 3) * 4;

    float acc[4][4] = {};
    for (int k0 = kbeg; k0 < kend; k0 += 16) {
        float4 av = *(const float4*)&d_cst[(size_t)(m0 + lrow) * Cz + k0 + lk4];
        As[lk4 + 0][lrow] = av.x; As[lk4 + 1][lrow] = av.y;
        As[lk4 + 2][lrow] = av.z; As[lk4 + 3][lrow] = av.w;
        int j = j0 + lrow;
        float4 wv = make_float4(0.f, 0.f, 0.f, 0.f);
        if (j < Nc) wv = *(const float4*)&W[(size_t)j * Cz + k0 + lk4];
        Ws[lk4 + 0][lrow] = wv.x; Ws[lk4 + 1][lrow] = wv.y;
        Ws[lk4 + 2][lrow] = wv.z; Ws[lk4 + 3][lrow] = wv.w;
        __syncthreads();
#pragma unroll
        for (int kk = 0; kk < 16; ++kk) {
            float4 a4 = *(const float4*)&As[kk][ty * 4];
            float4 w4 = *(const float4*)&Ws[kk][tx * 4];
            acc[0][0] += a4.x * w4.x; acc[0][1] += a4.x * w4.y;
            acc[0][2] += a4.x * w4.z; acc[0][3] += a4.x * w4.w;
            acc[1][0] += a4.y * w4.x; acc[1][1] += a4.y * w4.y;
            acc[1][2] += a4.y * w4.z; acc[1][3] += a4.y * w4.w;
            acc[2][0] += a4.z * w4.x; acc[2][1] += a4.z * w4.y;
            acc[2][2] += a4.z * w4.z; acc[2][3] += a4.z * w4.w;
            acc[3][0] += a4.w * w4.x; acc[3][1] += a4.w * w4.y;
            acc[3][2] += a4.w * w4.z; acc[3][3] += a4.w * w4.w;
        }
        __syncthreads();
    }
#pragma unroll
    for (int i = 0; i < 4; ++i) {
        int m = m0 + ty * 4 + i;
#pragma unroll
        for (int jj = 0; jj < 4; ++jj) {
            int j = j0 + tx * 4 + jj;
            if (j < Nc) out[(size_t)m * Nc + j] = acc[i][jj];
        }
    }
}

// ---------------- LSTM activations (sums K-split partials + bias) -------------
__global__ void lstm_act(const float* __restrict__ c0,
                         const float* __restrict__ b_ih,
                         const float* __restrict__ b_hh) {
    int idx = blockIdx.x * 256 + threadIdx.x;   // Bz*Cz
    int b = idx >> 9, j = idx & 511;
    const size_t off2 = (size_t)Bz * G4;
    const float* g0 = d_gatesP + (size_t)b * G4;
    const float* g1 = d_gatesP + off2 + (size_t)b * G4;
    float ig = g0[j]        + g1[j]        + b_ih[j]        + b_hh[j];
    float fg = g0[512 + j]  + g1[512 + j]  + b_ih[512 + j]  + b_hh[512 + j];
    float gg = g0[1024 + j] + g1[1024 + j] + b_ih[1024 + j] + b_hh[1024 + j];
    float og = g0[1536 + j] + g1[1536 + j] + b_ih[1536 + j] + b_hh[1536 + j];
    float c = sigm(fg) * c0[idx] + sigm(ig) * tanhf(gg);
    d_cst[idx] = c;
    d_hst[idx] = sigm(og) * tanhf(c);
}

// ---------------- per-head derived parameters (sums K-split partials) ---------
// Runs AFTER pass0 (which computes its own pair-0 keys from d_PpP directly).
__global__ void head_params(const float* __restrict__ b_addr,
                            const float* __restrict__ b_ea) {
    int hi = blockIdx.x, b = blockIdx.y, m = threadIdx.x;   // 64 threads
    __shared__ float sm[64];

    float pv = b_addr[hi * 70 + m];
#pragma unroll
    for (int s = 0; s < 4; ++s)
        pv += d_PpP[(size_t)s * Bz * PN + (size_t)b * PN + hi * 70 + m];
    float k = tanhf(pv);
    d_key[(hi * Bz + b) * 64 + m] = k;
    sm[m] = k * k;
    __syncthreads();
    for (int s = 32; s; s >>= 1) { if (m < s) sm[m] += sm[m + s]; __syncthreads(); }
    if (m == 0) {
        float tail[6];
#pragma unroll
        for (int t = 0; t < 6; ++t) {
            float v = b_addr[hi * 70 + 64 + t];
#pragma unroll
            for (int s = 0; s < 4; ++s)
                v += d_PpP[(size_t)s * Bz * PN + (size_t)b * PN + hi * 70 + 64 + t];
            tail[t] = v;
        }
        d_knorm[hi * Bz + b] = sqrtf(sm[0]);
        d_betaA[hi * Bz + b] = softplusf(tail[0]);
        d_gateA[hi * Bz + b] = sigm(tail[1]);
        float a0 = tail[2], a1 = tail[3], a2 = tail[4];
        float mx = fmaxf(a0, fmaxf(a1, a2));
        float e0 = __expf(a0 - mx), e1 = __expf(a1 - mx), e2 = __expf(a2 - mx);
        float is = 1.f / (e0 + e1 + e2);
        d_shiftA[(hi * Bz + b) * 3 + 0] = e0 * is;
        d_shiftA[(hi * Bz + b) * 3 + 1] = e1 * is;
        d_shiftA[(hi * Bz + b) * 3 + 2] = e2 * is;
        d_gammaA[hi * Bz + b] = 1.f + softplusf(tail[5]);
    }
    if (hi < 4) {
        float e = b_ea[hi * 128 + m];
        float a = b_ea[hi * 128 + 64 + m];
#pragma unroll
        for (int s = 0; s < 4; ++s) {
            e += d_EApP[(size_t)s * Bz * EAN + (size_t)b * EAN + hi * 128 + m];
            a += d_EApP[(size_t)s * Bz * EAN + (size_t)b * EAN + hi * 128 + 64 + m];
        }
        d_eA[(hi * Bz + b) * 64 + m] = sigm(e);
        d_aA[(hi * Bz + b) * 64 + m] = tanhf(a);
    }
}

// ---------------- big memory passes (scalar FMA) -------------------------------
// Pass L: recompute chain of writes 0..L-2 from mem0; read with wr[L-1];
// apply write L-1; dots for pair L (skip write-head dot at L==3; none at L==4).
// Pass 0: occ 5, batch 4 (44 regs <= 51 cap).
// Passes 1/2/4: occ 3, batch 2 (reg estimate 55-70 <= 85 cap).
// Pass 3: occ 2, batch 4 (known-good heavy config; regs > 85 would spill at occ 3).
template <int L>
__global__ void __launch_bounds__(256, (L == 0) ? 5 : ((L == 3) ? 2 : 3))
pass_kernel(const float* __restrict__ mem0, const float* __restrict__ b_addr) {
    const int b = blockIdx.y;
    const int n0 = blockIdx.x * 256;
    const int tid = threadIdx.x;
    const int g = tid >> 4, t = tid & 15;
    const int tm = t * 4;
    const size_t bN = (size_t)b * Nz;

    __shared__ float e_s[3][64], a_s[3][64];
    __shared__ float kr_s[64], kw_s[64];
    __shared__ float red[16][64];

    constexpr int NH  = (L < 3) ? L : 3;         // e/a vectors 0..NH-1
    constexpr int NWS = (L < 3) ? L : 3;         // ww streams read
    constexpr bool DOTS = (L <= 3);
    constexpr bool DOTW = (L < 3);
    constexpr int JA = (L >= 1) ? (L - 1) : 0;   // applied write index
    constexpr int U   = (L == 0 || L == 3) ? 4 : 2;   // row batch per iter
    constexpr int NIT = 16 / U;

    for (int idx = tid; idx < NH * 64; idx += 256) {
        int j = idx >> 6, m = idx & 63;
        e_s[j][m] = d_eA[(j * Bz + b) * 64 + m];
        a_s[j][m] = d_aA[(j * Bz + b) * 64 + m];
    }
    if (L == 0) {
        // self-compute pair-0 keys from GEMM partials (head_params not yet run)
        if (tid < 128) {
            int hi = tid >> 6, m = tid & 63;
            float pv = b_addr[hi * 70 + m];
#pragma unroll
            for (int s = 0; s < 4; ++s)
                pv += d_PpP[(size_t)s * Bz * PN + (size_t)b * PN + hi * 70 + m];
            float k = tanhf(pv);
            if (hi == 0) kr_s[m] = k; else kw_s[m] = k;
        }
    } else if (DOTS) {
        if (tid < 64) kr_s[tid] = d_key[((2 * L) * Bz + b) * 64 + tid];
        else if (DOTW && tid < 128)
            kw_s[tid - 64] = d_key[((2 * L + 1) * Bz + b) * 64 + (tid - 64)];
    }
    __syncthreads();

    // hoist per-column params to registers (scalar)
    float ne[NH > 0 ? NH : 1][4], aa[NH > 0 ? NH : 1][4];
#pragma unroll
    for (int j = 0; j < NH; ++j)
#pragma unroll
        for (int x = 0; x < 4; ++x) {
            ne[j][x] = -e_s[j][tm + x];
            aa[j][x] =  a_s[j][tm + x];
        }
    float kr[4] = {}, kw[4] = {};
    if (DOTS) {
#pragma unroll
        for (int x = 0; x < 4; ++x) kr[x] = kr_s[tm + x];
        if (DOTW)
#pragma unroll
            for (int x = 0; x < 4; ++x) kw[x] = kw_s[tm + x];
    }

    float r0 = 0.f, r1 = 0.f, r2 = 0.f, r3 = 0.f;
    const float* base = mem0 + (((size_t)(bN + n0)) << 6);

#pragma unroll
    for (int rr = 0; rr < NIT; ++rr) {
        const int nb = rr * (U * 16);
        float4 v[U];
        float wj[NWS > 0 ? NWS : 1][U];
        float wrv[U];
        // ---- batch global loads first ----
#pragma unroll
        for (int u = 0; u < U; ++u) {
            int row = nb + u * 16 + g;
            v[u] = *(const float4*)(base + (((size_t)row) << 6) + tm);
        }
#pragma unroll
        for (int u = 0; u < U; ++u) {
            int n = n0 + nb + u * 16 + g;
#pragma unroll
            for (int j = 0; j < NWS; ++j)
                wj[j][u] = __ldg(&d_ww[(size_t)j * Bz * Nz + bN + n]);
            if (L >= 1) wrv[u] = __ldg(&d_wr[(size_t)(L - 1) * Bz * Nz + bN + n]);
        }
        // ---- compute ----
#pragma unroll
        for (int u = 0; u < U; ++u) {
            float4 vv = v[u];
            int n = n0 + nb + u * 16 + g;
            // chain writes 0..L-2:  v' = fma(w, fma(-e, v, a), v)
#pragma unroll
            for (int j = 0; j < NH; ++j) {
                if (j < L - 1) {
                    float w = wj[j][u];
                    vv.x = fmaf(w, fmaf(ne[j][0], vv.x, aa[j][0]), vv.x);
                    vv.y = fmaf(w, fmaf(ne[j][1], vv.y, aa[j][1]), vv.y);
                    vv.z = fmaf(w, fmaf(ne[j][2], vv.z, aa[j][2]), vv.z);
                    vv.w = fmaf(w, fmaf(ne[j][3], vv.w, aa[j][3]), vv.w);
                }
            }
            if (L >= 1) {
                float w = wrv[u];
                r0 = fmaf(w, vv.x, r0); r1 = fmaf(w, vv.y, r1);
                r2 = fmaf(w, vv.z, r2); r3 = fmaf(w, vv.w, r3);
                if (L <= 3) {
                    float wa = wj[JA][u];
                    vv.x = fmaf(wa, fmaf(ne[JA][0], vv.x, aa[JA][0]), vv.x);
                    vv.y = fmaf(wa, fmaf(ne[JA][1], vv.y, aa[JA][1]), vv.y);
                    vv.z = fmaf(wa, fmaf(ne[JA][2], vv.z, aa[JA][2]), vv.z);
                    vv.w = fmaf(wa, fmaf(ne[JA][3], vv.w, aa[JA][3]), vv.w);
                }
            }
            if (DOTS) {
                float pr = vv.x * kr[0] + vv.y * kr[1] + vv.z * kr[2] + vv.w * kr[3];
                float pn = vv.x * vv.x + vv.y * vv.y + vv.z * vv.z + vv.w * vv.w;
                float pw = 0.f;
                if (DOTW)
                    pw = vv.x * kw[0] + vv.y * kw[1] + vv.z * kw[2] + vv.w * kw[3];
#pragma unroll
                for (int off = 8; off; off >>= 1) {
                    pr += __shfl_down_sync(0xffffffffu, pr, off, 16);
                    pn += __shfl_down_sync(0xffffffffu, pn, off, 16);
                    if (DOTW) pw += __shfl_down_sync(0xffffffffu, pw, off, 16);
                }
                if (t == 0) {
                    d_dotr[bN + n] = pr;
                    d_rn[bN + n] = sqrtf(pn);
                    if (DOTW) d_dotw[bN + n] = pw;
                }
            }
        }
    }

    if (L >= 1) {
        red[g][tm + 0] = r0; red[g][tm + 1] = r1;
        red[g][tm + 2] = r2; red[g][tm + 3] = r3;
        __syncthreads();
        if (tid < 64) {
            float s = 0.f;
#pragma unroll
            for (int gg = 0; gg < 16; ++gg) s += red[gg][tid];
            d_readpart[(((L - 1) * NTILES + blockIdx.x) * Bz + b) * 64 + tid] = s;
        }
    }
}

// ---------------- addressing: softmax / interpolate / shift / sharpen --------
__global__ void weights_kernel(int pair, const float* __restrict__ prevw) {
    const int b = blockIdx.y;
    const int hsub = blockIdx.x;
    const int head = 2 * pair + hsub;
    const float* __restrict__ dot = hsub ? d_dotw : d_dotr;
    const int tid = threadIdx.x;    // 256
    __shared__ float wg_s[Nz];
    __shared__ float red[256];

    const size_t bN = (size_t)b * Nz;
    const float beta  = d_betaA[head * Bz + b];
    const float gate  = d_gateA[head * Bz + b];
    const float gamma = d_gammaA[head * Bz + b];
    const float s0 = d_shiftA[(head * Bz + b) * 3 + 0];
    const float s1 = d_shiftA[(head * Bz + b) * 3 + 1];
    const float s2 = d_shiftA[(head * Bz + b) * 3 + 2];
    const float kn = d_knorm[head * Bz + b];

    float lg[16];
    float lmax = -1e30f;
#pragma unroll
    for (int r = 0; r < 16; ++r) {
        int n = tid + r * 256;
        float l = __fdividef(beta * dot[bN + n], d_rn[bN + n] * kn + 1e-8f);
        lg[r] = l;
        lmax = fmaxf(lmax, l);
    }
    red[tid] = lmax; __syncthreads();
    for (int s = 128; s; s >>= 1) { if (tid < s) red[tid] = fmaxf(red[tid], red[tid + s]); __syncthreads(); }
    lmax = red[0]; __syncthreads();

    float esum = 0.f;
#pragma unroll
    for (int r = 0; r < 16; ++r) {
        float e = __expf(lg[r] - lmax);
        wg_s[tid + r * 256] = e;
        esum += e;
    }
    red[tid] = esum; __syncthreads();
    for (int s = 128; s; s >>= 1) { if (tid < s) red[tid] += red[tid + s]; __syncthreads(); }
    float inv = 1.f / red[0]; __syncthreads();

#pragma unroll
    for (int r = 0; r < 16; ++r) {
        int n = tid + r * 256;
        wg_s[n] = gate * (wg_s[n] * inv)
                + (1.f - gate) * prevw[(size_t)head * Bz * Nz + bN + n];
    }
    __syncthreads();

    float wp[16];
    float psum = 0.f;
#pragma unroll
    for (int r = 0; r < 16; ++r) {
        int n = tid + r * 256;
        float ws = s0 * wg_s[(n + Nz - 1) & (Nz - 1)]
                 + s1 * wg_s[n]
                 + s2 * wg_s[(n + 1) & (Nz - 1)];
        float p = __powf(ws, gamma);
        wp[r] = p;
        psum += p;
    }
    red[tid] = psum; __syncthreads();
    for (int s = 128; s; s >>= 1) { if (tid < s) red[tid] += red[tid + s]; __syncthreads(); }
    float invp = 1.f / (red[0] + 1e-8f);

    float* __restrict__ wout = hsub ? (d_ww + (size_t)pair * Bz * Nz)
                                    : (d_wr + (size_t)pair * Bz * Nz);
#pragma unroll
    for (int r = 0; r < 16; ++r) {
        int n = tid + r * 256;
        wout[bN + n] = wp[r] * invp;
    }
}

// ---------------- finalize reads ---------------------------------------------
__global__ void reduce_reads() {
    int idx = blockIdx.x * 256 + threadIdx.x;   // 4*Bz*64
    if (idx >= 4 * Bz * 64) return;
    int i = idx / (Bz * 64), rem = idx - i * (Bz * 64);
    float s = 0.f;
#pragma unroll
    for (int t = 0; t < NTILES; ++t)
        s += d_readpart[(i * NTILES + t) * (Bz * 64) + rem];
    d_reads[idx] = s;
}

// ---------------- output layer -----------------------------------------------
__global__ void out_kernel(const float* __restrict__ Wout,
                           const float* __restrict__ bout,
                           float* __restrict__ out) {
    int b = blockIdx.x, o = threadIdx.x;    // 64 threads
    const float* wrow = Wout + (size_t)o * 768;
    const float* hh = d_hst + (size_t)b * Cz;
    float a0 = 0.f, a1 = 0.f, a2 = 0.f, a3 = 0.f;
    for (int k = 0; k < 512; k += 4) {
        a0 += hh[k] * wrow[k];         a1 += hh[k + 1] * wrow[k + 1];
        a2 += hh[k + 2] * wrow[k + 2]; a3 += hh[k + 3] * wrow[k + 3];
    }
#pragma unroll
    for (int i = 0; i < 4; ++i) {
        const float* rr = d_reads + (size_t)(i * Bz + b) * 64;
        const float* w2 = wrow + 512 + i * 64;
        for (int m = 0; m < 64; m += 4) {
            a0 += rr[m] * w2[m];           a1 += rr[m + 1] * w2[m + 1];
            a2 += rr[m + 2] * w2[m + 2];   a3 += rr[m + 3] * w2[m + 3];
        }
    }
    float s = a0 + a1 + a2 + a3 + bout[o];
    out[(size_t)b * 64 + o] = 1.f / (1.f + __expf(-s));
}

// ---------------- launch -----------------------------------------------------
extern "C" void kernel_launch(void* const* d_in, const int* in_sizes, int n_in,
                              void* d_out, int out_size) {
    const float* in_data = (const float*)d_in[0];
    const float* memory  = (const float*)d_in[1];
    const float* h0      = (const float*)d_in[2];
    const float* c0      = (const float*)d_in[3];
    const float* prevw   = (const float*)d_in[4];
    const float* prevr   = (const float*)d_in[5];
    const float* W_ih    = (const float*)d_in[6];
    const float* b_ih    = (const float*)d_in[7];
    const float* W_hh    = (const float*)d_in[8];
    const float* b_hh    = (const float*)d_in[9];
    const float* W_out   = (const float*)d_in[10];
    const float* b_out   = (const float*)d_in[11];
    const float* W_addr  = (const float*)d_in[12];
    const float* b_addr  = (const float*)d_in[13];
    const float* W_ea    = (const float*)d_in[14];
    const float* b_ea    = (const float*)d_in[15];
    float* out = (float*)d_out;

    gemm_gates<<<dim3(G4 / 64, Bz / 64, 2), 256>>>(W_ih, W_hh, in_data, prevr, h0);
    lstm_act<<<Bz * Cz / 256, 256>>>(c0, b_ih, b_hh);
    gemm_addr<<<dim3((PN + 63) / 64, Bz / 64, 8), 256>>>(W_addr, W_ea);

    pass_kernel<0><<<dim3(NTILES, Bz), 256>>>(memory, b_addr);   // 4th launch -> profiled
    head_params<<<dim3(8, Bz), 64>>>(b_addr, b_ea);
    weights_kernel<<<dim3(2, Bz), 256>>>(0, prevw);
    pass_kernel<1><<<dim3(NTILES, Bz), 256>>>(memory, b_addr);
    weights_kernel<<<dim3(2, Bz), 256>>>(1, prevw);
    pass_kernel<2><<<dim3(NTILES, Bz), 256>>>(memory, b_addr);
    weights_kernel<<<dim3(2, Bz), 256>>>(2, prevw);
    pass_kernel<3><<<dim3(NTILES, Bz), 256>>>(memory, b_addr);
    weights_kernel<<<dim3(1, Bz), 256>>>(3, prevw);   // head 6 only; head 7 write is dead
    pass_kernel<4><<<dim3(NTILES, Bz), 256>>>(memory, b_addr);

    reduce_reads<<<(4 * Bz * 64 + 255) / 256, 256>>>();
    out_kernel<<<Bz, 64>>>(W_out, b_out, out);
}